// round 3
// baseline (speedup 1.0000x reference)
#include <cuda_runtime.h>
#include <math.h>
#include <stdint.h>

// Problem constants (from reference)
#define B_    16
#define T_    1024
#define IN_   1024
#define MEM_  64
#define OUT_  1024
#define C_    32                     // CTX/2
#define HN_   (2*MEM_ + 2*OUT_)      // 2176
#define NTOK  (B_*T_)                // 16384
#define KMIX  (MEM_*2*C_)            // 4096

// Scratch (device-global: no allocation allowed in kernel_launch)
__device__ float g_h [(size_t)NTOK * HN_];   // pre-projection h                       (~143 MB)
__device__ float g_y [(size_t)NTOK * MEM_];  // gated scan input                       (~4 MB)
__device__ float g_z [(size_t)NTOK * OUT_];  // mix output before layernorm            (~67 MB)
__device__ float g_sr[(size_t)NTOK * KMIX];  // interleaved complex states == sr       (~268 MB)

// ---------------------------------------------------------------------------
// Generic NT GEMM: C[M,N] = A[M,K] @ B[N,K]^T + bias[N]
// 128x128 tile, 256 threads, 8x8 microtile, TK=8.
// ---------------------------------------------------------------------------
__global__ __launch_bounds__(256, 2)
void gemm128(const float* __restrict__ A, const float* __restrict__ Bw,
             const float* __restrict__ bias, float* __restrict__ Cout,
             int K, int ldc)
{
    __shared__ float As[8][128];
    __shared__ float Bs[8][128];
    const int bm  = blockIdx.y << 7;
    const int bn  = blockIdx.x << 7;
    const int tid = threadIdx.x;
    const int tx  = tid & 15;
    const int ty  = tid >> 4;
    const int lrow = tid >> 1;
    const int lc   = (tid & 1) << 2;

    const float* Ag = A  + (size_t)(bm + lrow) * K + lc;
    const float* Bg = Bw + (size_t)(bn + lrow) * K + lc;

    float acc[8][8];
#pragma unroll
    for (int i = 0; i < 8; ++i)
#pragma unroll
        for (int j = 0; j < 8; ++j) acc[i][j] = 0.f;

    for (int k0 = 0; k0 < K; k0 += 8) {
        float4 av = *(const float4*)(Ag + k0);
        float4 bv = *(const float4*)(Bg + k0);
        As[lc+0][lrow] = av.x; As[lc+1][lrow] = av.y;
        As[lc+2][lrow] = av.z; As[lc+3][lrow] = av.w;
        Bs[lc+0][lrow] = bv.x; Bs[lc+1][lrow] = bv.y;
        Bs[lc+2][lrow] = bv.z; Bs[lc+3][lrow] = bv.w;
        __syncthreads();
#pragma unroll
        for (int k = 0; k < 8; ++k) {
            float4 a0 = *(const float4*)&As[k][(ty<<3)];
            float4 a1 = *(const float4*)&As[k][(ty<<3) + 4];
            float4 b0 = *(const float4*)&Bs[k][(tx<<3)];
            float4 b1 = *(const float4*)&Bs[k][(tx<<3) + 4];
            float ar[8] = {a0.x,a0.y,a0.z,a0.w,a1.x,a1.y,a1.z,a1.w};
            float br[8] = {b0.x,b0.y,b0.z,b0.w,b1.x,b1.y,b1.z,b1.w};
#pragma unroll
            for (int i = 0; i < 8; ++i)
#pragma unroll
                for (int j = 0; j < 8; ++j)
                    acc[i][j] = fmaf(ar[i], br[j], acc[i][j]);
        }
        __syncthreads();
    }

    const int ccol = bn + (tx << 3);
    float bb[8];
#pragma unroll
    for (int j = 0; j < 8; ++j) bb[j] = bias[ccol + j];
#pragma unroll
    for (int i = 0; i < 8; ++i) {
        const int row = bm + (ty << 3) + i;
        float4 o0 = make_float4(acc[i][0]+bb[0], acc[i][1]+bb[1],
                                acc[i][2]+bb[2], acc[i][3]+bb[3]);
        float4 o1 = make_float4(acc[i][4]+bb[4], acc[i][5]+bb[5],
                                acc[i][6]+bb[6], acc[i][7]+bb[7]);
        *(float4*)(Cout + (size_t)row * ldc + ccol)     = o0;
        *(float4*)(Cout + (size_t)row * ldc + ccol + 4) = o1;
    }
}

// ---------------------------------------------------------------------------
// Gating: y[t,m] = h[t,m] * sigmoid(h[t, MEM+OUT+m])
// ---------------------------------------------------------------------------
__global__ void gating_kernel()
{
    int g = blockIdx.x * blockDim.x + threadIdx.x;     // over NTOK*MEM_
    int t = g >> 6;
    int m = g & 63;
    const float* hr = g_h + (size_t)t * HN_;
    float hy = hr[m];
    float hg = hr[MEM_ + OUT_ + m];
    g_y[g] = hy * (1.f / (1.f + expf(-hg)));
}

// ---------------------------------------------------------------------------
// Complex diagonal scan: s_t = gamma * s_{t-1} + y_t  (s_{-1}=0)
// One thread per (b, m, c) chain. Writes:
//   st      : interleaved float2 (== sr matrix for GEMM2; == complex64 layout)
//   st_real : optional real-part-only float32 (harness's coerced states output)
// ---------------------------------------------------------------------------
__global__ void scan_kernel(const float* __restrict__ a,
                            const float* __restrict__ bfreq,
                            float2* __restrict__ st,
                            float*  __restrict__ st_real)
{
    int g = blockIdx.x * blockDim.x + threadIdx.x;     // 0 .. B*MEM*C-1
    int c = g & (C_ - 1);
    int m = (g >> 5) & (MEM_ - 1);
    int b = g >> 11;

    float r   = expf(-fabsf(a[m]));
    float ang = bfreq[c];
    float gr  = r * cosf(ang);
    float gi  = r * sinf(ang);

    const float* yb = g_y + (size_t)b * T_ * MEM_ + m;
    const size_t base = ((size_t)b * T_ * MEM_ + m) * C_ + c;
    float2* sb = st + base;
    float*  rb = st_real ? st_real + base : 0;

    float sr = 0.f, si = 0.f;
    for (int t = 0; t < T_; ++t) {
        float yv = yb[(size_t)t * MEM_];
        float nr = fmaf(gr, sr, fmaf(-gi, si, yv));
        float ni = fmaf(gr, si, gi * sr);
        sr = nr; si = ni;
        sb[(size_t)t * (MEM_ * C_)] = make_float2(sr, si);
        if (rb) rb[(size_t)t * (MEM_ * C_)] = sr;
    }
}

// ---------------------------------------------------------------------------
// Layernorm + gated mix epilogue
// ---------------------------------------------------------------------------
__global__ __launch_bounds__(256)
void ln_epilogue(float* __restrict__ out)
{
    __shared__ float red[256];
    const int row = blockIdx.x;
    const int tid = threadIdx.x;
    const float* zr = g_z + (size_t)row * OUT_;

    float v[4];
    float s = 0.f;
#pragma unroll
    for (int j = 0; j < 4; ++j) { v[j] = zr[tid + (j << 8)]; s += v[j]; }

    red[tid] = s; __syncthreads();
    for (int off = 128; off > 0; off >>= 1) {
        if (tid < off) red[tid] += red[tid + off];
        __syncthreads();
    }
    float mu = red[0] * (1.f / OUT_);
    __syncthreads();

    float ss = 0.f;
#pragma unroll
    for (int j = 0; j < 4; ++j) { float d = v[j] - mu; ss += d * d; }
    red[tid] = ss; __syncthreads();
    for (int off = 128; off > 0; off >>= 1) {
        if (tid < off) red[tid] += red[tid + off];
        __syncthreads();
    }
    float inv = rsqrtf(red[0] * (1.f / OUT_) + 1e-5f);

    const float* hr = g_h + (size_t)row * HN_;
#pragma unroll
    for (int j = 0; j < 4; ++j) {
        int o = tid + (j << 8);
        float og   = 1.f / (1.f + expf(-hr[MEM_ + OUT_ + MEM_ + o]));
        float thru = hr[MEM_ + o];
        out[(size_t)row * OUT_ + o] = (v[j] - mu) * inv * og + thru * (1.f - og);
    }
}

// ---------------------------------------------------------------------------
extern "C" void kernel_launch(void* const* d_in, const int* in_sizes, int n_in,
                              void* d_out, int out_size)
{
    (void)in_sizes; (void)n_in;
    const float* x     = (const float*)d_in[0];
    const float* pre_w = (const float*)d_in[1];
    const float* pre_b = (const float*)d_in[2];
    const float* a     = (const float*)d_in[3];
    const float* bfr   = (const float*)d_in[4];
    const float* mix_w = (const float*)d_in[5];
    const float* mix_b = (const float*)d_in[6];
    float* out = (float*)d_out;

    float *hbuf, *zbuf, *srbuf;
    cudaGetSymbolAddress((void**)&hbuf,  g_h);
    cudaGetSymbolAddress((void**)&zbuf,  g_z);
    cudaGetSymbolAddress((void**)&srbuf, g_sr);

    const long long OUT_ELEMS = (long long)NTOK * OUT_;        // 16,777,216
    const long long ST_CPLX_F = 2LL * NTOK * MEM_ * C_;        // 67,108,864 (interleaved floats)
    const long long ST_REAL_F = (long long)NTOK * MEM_ * C_;   // 33,554,432 (real-only floats)
    const long long avail = (long long)out_size - OUT_ELEMS;   // floats past `out`

    // Decide destinations based on the actual buffer size (never write OOB):
    //  - If d_out can hold full interleaved complex states, write them there
    //    directly (GEMM2 reads them in place, no extra copy).
    //  - Else if it holds the real-part-only view (harness float32-coerces the
    //    complex64 output), write real part there + interleaved to scratch.
    //  - Else keep everything in scratch (output 0 still exact).
    float2* st_interleaved;
    float*  st_real;
    if (avail >= ST_CPLX_F) {
        st_interleaved = (float2*)(out + OUT_ELEMS);
        st_real = 0;
    } else if (avail >= ST_REAL_F) {
        st_interleaved = (float2*)srbuf;
        st_real = out + OUT_ELEMS;
    } else {
        st_interleaved = (float2*)srbuf;
        st_real = 0;
    }

    // 1) h = x @ pre_w^T + pre_b        (M=16384, N=2176, K=1024)
    gemm128<<<dim3(HN_/128, NTOK/128), 256>>>(x, pre_w, pre_b, hbuf, IN_, HN_);
    // 2) y = h[:, :64] * sigmoid(h[:, 1088:1152])
    gating_kernel<<<(NTOK * MEM_) / 256, 256>>>();
    // 3) complex scan -> states
    scan_kernel<<<(B_ * MEM_ * C_) / 256, 256>>>(a, bfr, st_interleaved, st_real);
    // 4) z = sr @ mix_w^T + mix_b       (M=16384, N=1024, K=4096)
    gemm128<<<dim3(OUT_/128, NTOK/128), 256>>>((const float*)st_interleaved,
                                               mix_w, mix_b, zbuf, KMIX, OUT_);
    // 5) out = LN(z)*out_gate + thru*(1-out_gate)
    ln_epilogue<<<NTOK, 256>>>(out);
}

// round 5
// speedup vs baseline: 2.4674x; 2.4674x over previous
#include <cuda_runtime.h>
#include <cuda_bf16.h>
#include <math.h>
#include <stdint.h>

// ---------------------------------------------------------------- constants
#define B_    16
#define T_    1024
#define IN_   1024
#define MEM_  64
#define OUT_  1024
#define C_    32
#define HN_   (2*MEM_ + 2*OUT_)      // 2176
#define NTOK  (B_*T_)                // 16384
#define KMIX  (MEM_*2*C_)            // 4096

// ---------------------------------------------------------------- scratch
__device__ float g_h [(size_t)NTOK * HN_];
__device__ float g_y [(size_t)NTOK * MEM_];
__device__ float g_z [(size_t)NTOK * OUT_];
__device__ __nv_bfloat16 g_xh [(size_t)NTOK * IN_];
__device__ __nv_bfloat16 g_xl [(size_t)NTOK * IN_];
__device__ __nv_bfloat16 g_w1h[(size_t)HN_  * IN_];
__device__ __nv_bfloat16 g_w1l[(size_t)HN_  * IN_];
__device__ __nv_bfloat16 g_w2h[(size_t)OUT_ * KMIX];
__device__ __nv_bfloat16 g_w2l[(size_t)OUT_ * KMIX];
__device__ __nv_bfloat16 g_srh[(size_t)NTOK * KMIX];
__device__ __nv_bfloat16 g_srl[(size_t)NTOK * KMIX];

// ---------------------------------------------------------------- utils
__device__ __forceinline__ uint32_t smem_u32_of(const void* p) {
    uint32_t a;
    asm("{ .reg .u64 t; cvta.to.shared.u64 t, %1; cvt.u32.u64 %0, t; }"
        : "=r"(a) : "l"(p));
    return a;
}

#define LDSM4(r0, r1, r2, r3, addr)                                         \
    asm volatile("ldmatrix.sync.aligned.m8n8.x4.shared.b16 {%0,%1,%2,%3}, [%4];" \
        : "=r"(r0), "=r"(r1), "=r"(r2), "=r"(r3) : "r"(addr))

#define MMA_BF16(c, a, b)                                                   \
    asm volatile("mma.sync.aligned.m16n8k16.row.col.f32.bf16.bf16.f32 "     \
        "{%0,%1,%2,%3}, {%4,%5,%6,%7}, {%8,%9}, {%0,%1,%2,%3};"             \
        : "+f"((c)[0]), "+f"((c)[1]), "+f"((c)[2]), "+f"((c)[3])            \
        : "r"((a)[0]), "r"((a)[1]), "r"((a)[2]), "r"((a)[3]),               \
          "r"((b)[0]), "r"((b)[1]))

#define CP_ASYNC16(sp, gp)                                                  \
    asm volatile("cp.async.cg.shared.global [%0], [%1], 16;"                \
        :: "r"(sp), "l"(gp))
#define CP_COMMIT()   asm volatile("cp.async.commit_group;" ::: "memory")
#define CP_WAIT_1()   asm volatile("cp.async.wait_group 1;" ::: "memory")
#define CP_WAIT_0()   asm volatile("cp.async.wait_group 0;" ::: "memory")

// ---------------------------------------------------------------- split
__global__ void split_kernel(const float* __restrict__ src,
                             __nv_bfloat16* __restrict__ hi,
                             __nv_bfloat16* __restrict__ lo, int n4)
{
    int i = blockIdx.x * blockDim.x + threadIdx.x;
    if (i >= n4) return;
    float4 v = ((const float4*)src)[i];
    __nv_bfloat16 h0 = __float2bfloat16_rn(v.x);
    __nv_bfloat16 h1 = __float2bfloat16_rn(v.y);
    __nv_bfloat16 h2 = __float2bfloat16_rn(v.z);
    __nv_bfloat16 h3 = __float2bfloat16_rn(v.w);
    __nv_bfloat16 l0 = __float2bfloat16_rn(v.x - __bfloat162float(h0));
    __nv_bfloat16 l1 = __float2bfloat16_rn(v.y - __bfloat162float(h1));
    __nv_bfloat16 l2 = __float2bfloat16_rn(v.z - __bfloat162float(h2));
    __nv_bfloat16 l3 = __float2bfloat16_rn(v.w - __bfloat162float(h3));
    ((__nv_bfloat162*)hi)[i*2+0] = __halves2bfloat162(h0, h1);
    ((__nv_bfloat162*)hi)[i*2+1] = __halves2bfloat162(h2, h3);
    ((__nv_bfloat162*)lo)[i*2+0] = __halves2bfloat162(l0, l1);
    ((__nv_bfloat162*)lo)[i*2+1] = __halves2bfloat162(l2, l3);
}

// ---------------------------------------------------------------- MMA GEMM
// C[M,N] = Ah@Bh^T + Ah@Bl^T + Al@Bh^T + bias (fp32 accum, mma.sync bf16)
// CTA tile 128x128, 8 warps (warp tile 64x32), K-chunk 64, double-buffered
// cp.async. Smem rows padded to 72 bf16 (144B) -> conflict-free ldmatrix.
#define PADW    72
#define TB      (128 * PADW * 2)           // bytes per tensor tile: 18432
#define STG_B   (4 * TB)                   // bytes per stage: 73728
#define SMEM_MMA (2 * STG_B)               // 147456

__device__ __forceinline__ void ld_tile_async(uint32_t sdst,
                                              const __nv_bfloat16* __restrict__ g,
                                              int row0, int K, int k0, int tid)
{
#pragma unroll
    for (int it = 0; it < 4; ++it) {
        int idx = tid + (it << 8);          // 0..1023 16B vectors
        int row = idx >> 3, c8 = idx & 7;
        const void* gp = g + (size_t)(row0 + row) * K + k0 + c8 * 8;
        uint32_t sp = sdst + row * 144 + c8 * 16;
        CP_ASYNC16(sp, gp);
    }
}

__global__ __launch_bounds__(256, 1)
void gemm_mma(const __nv_bfloat16* __restrict__ Ah, const __nv_bfloat16* __restrict__ Al,
              const __nv_bfloat16* __restrict__ Bh, const __nv_bfloat16* __restrict__ Bl,
              const float* __restrict__ bias, float* __restrict__ Cout,
              int K, int N)
{
    extern __shared__ char smem[];
    const uint32_t smb = smem_u32_of(smem);
    const int tid  = threadIdx.x;
    const int wid  = tid >> 5;
    const int lane = tid & 31;
    const int bm   = blockIdx.y << 7;
    const int bn   = blockIdx.x << 7;
    const int m0   = (wid & 1) * 64;        // warp M offset in tile
    const int n0   = (wid >> 1) * 32;       // warp N offset in tile

    float acc[4][4][4];
#pragma unroll
    for (int i = 0; i < 4; ++i)
#pragma unroll
        for (int j = 0; j < 4; ++j)
#pragma unroll
            for (int k = 0; k < 4; ++k) acc[i][j][k] = 0.f;

    const int nk = K >> 6;

    // prologue: stage 0
    {
        uint32_t s0 = smb;
        ld_tile_async(s0,            Ah, bm, K, 0, tid);
        ld_tile_async(s0 + TB,       Al, bm, K, 0, tid);
        ld_tile_async(s0 + 2 * TB,   Bh, bn, K, 0, tid);
        ld_tile_async(s0 + 3 * TB,   Bl, bn, K, 0, tid);
        CP_COMMIT();
    }

    // per-lane ldmatrix address components
    const int arow  = (lane & 7) + ((lane >> 3) & 1) * 8;   // A: row within 16
    const int akoff = (lane >> 4) * 8;                      // A: k offset
    const int bgrp  = lane >> 3;
    const int brow  = (lane & 7) + (bgrp >> 1) * 8;         // B: n within 16
    const int bkoff = (bgrp & 1) * 8;                       // B: k offset

    for (int i = 0; i < nk; ++i) {
        if (i + 1 < nk) {
            uint32_t sn = smb + ((i + 1) & 1) * STG_B;
            int k0 = (i + 1) << 6;
            ld_tile_async(sn,          Ah, bm, K, k0, tid);
            ld_tile_async(sn + TB,     Al, bm, K, k0, tid);
            ld_tile_async(sn + 2 * TB, Bh, bn, K, k0, tid);
            ld_tile_async(sn + 3 * TB, Bl, bn, K, k0, tid);
            CP_COMMIT();
            CP_WAIT_1();
        } else {
            CP_WAIT_0();
        }
        __syncthreads();

        const uint32_t sA  = smb + (i & 1) * STG_B;
        const uint32_t sAh = sA;
        const uint32_t sAl = sA + TB;
        const uint32_t sBh = sA + 2 * TB;
        const uint32_t sBl = sA + 3 * TB;

#pragma unroll
        for (int kk = 0; kk < 4; ++kk) {
            uint32_t ah[4][4], al[4][4], bh[4][2], bl[4][2];
#pragma unroll
            for (int mt = 0; mt < 4; ++mt) {
                uint32_t aoff = (uint32_t)(m0 + mt * 16 + arow) * 144
                              + (uint32_t)(kk * 16 + akoff) * 2;
                LDSM4(ah[mt][0], ah[mt][1], ah[mt][2], ah[mt][3], sAh + aoff);
                LDSM4(al[mt][0], al[mt][1], al[mt][2], al[mt][3], sAl + aoff);
            }
#pragma unroll
            for (int hf = 0; hf < 2; ++hf) {
                uint32_t boff = (uint32_t)(n0 + hf * 16 + brow) * 144
                              + (uint32_t)(kk * 16 + bkoff) * 2;
                uint32_t t0, t1, t2, t3;
                LDSM4(t0, t1, t2, t3, sBh + boff);
                bh[hf*2][0] = t0; bh[hf*2][1] = t1;
                bh[hf*2+1][0] = t2; bh[hf*2+1][1] = t3;
                LDSM4(t0, t1, t2, t3, sBl + boff);
                bl[hf*2][0] = t0; bl[hf*2][1] = t1;
                bl[hf*2+1][0] = t2; bl[hf*2+1][1] = t3;
            }
#pragma unroll
            for (int mt = 0; mt < 4; ++mt)
#pragma unroll
                for (int nt = 0; nt < 4; ++nt) {
                    MMA_BF16(acc[mt][nt], ah[mt], bh[nt]);
                    MMA_BF16(acc[mt][nt], ah[mt], bl[nt]);
                    MMA_BF16(acc[mt][nt], al[mt], bh[nt]);
                }
        }
        __syncthreads();
    }

    // epilogue (+bias)
#pragma unroll
    for (int mt = 0; mt < 4; ++mt) {
#pragma unroll
        for (int nt = 0; nt < 4; ++nt) {
            int row = bm + m0 + mt * 16 + (lane >> 2);
            int col = bn + n0 + nt * 8 + 2 * (lane & 3);
            float b0 = bias[col], b1 = bias[col + 1];
            float2 v0 = make_float2(acc[mt][nt][0] + b0, acc[mt][nt][1] + b1);
            float2 v1 = make_float2(acc[mt][nt][2] + b0, acc[mt][nt][3] + b1);
            *(float2*)(Cout + (size_t)row * N + col)       = v0;
            *(float2*)(Cout + (size_t)(row + 8) * N + col) = v1;
        }
    }
}

// ---------------------------------------------------------------- gating
__global__ void gating_kernel()
{
    int g = blockIdx.x * blockDim.x + threadIdx.x;
    int t = g >> 6;
    int m = g & 63;
    const float* hr = g_h + (size_t)t * HN_;
    float hy = hr[m];
    float hg = hr[MEM_ + OUT_ + m];
    g_y[g] = hy * (1.f / (1.f + expf(-hg)));
}

// ---------------------------------------------------------------- scan
__global__ void scan_kernel(const float* __restrict__ a,
                            const float* __restrict__ bfreq,
                            float2* __restrict__ st,
                            float*  __restrict__ st_real)
{
    int g = blockIdx.x * blockDim.x + threadIdx.x;    // 0..B*MEM*C-1
    int c = g & (C_ - 1);
    int m = (g >> 5) & (MEM_ - 1);
    int b = g >> 11;

    float r   = expf(-fabsf(a[m]));
    float ang = bfreq[c];
    float gr  = r * cosf(ang);
    float gi  = r * sinf(ang);

    const float* yb = g_y + (size_t)b * T_ * MEM_ + m;
    const size_t base = ((size_t)b * T_ * MEM_ + m) * C_ + c;   // complex units
    float2* sb = st ? st + base : 0;
    float*  rb = st_real ? st_real + base : 0;
    __nv_bfloat162* sh = (__nv_bfloat162*)g_srh + base;
    __nv_bfloat162* sl = (__nv_bfloat162*)g_srl + base;

    float sr = 0.f, si = 0.f;
    for (int t = 0; t < T_; ++t) {
        float yv = yb[(size_t)t * MEM_];
        float nr = fmaf(gr, sr, fmaf(-gi, si, yv));
        float ni = fmaf(gr, si, gi * sr);
        sr = nr; si = ni;
        const size_t o = (size_t)t * (MEM_ * C_);
        if (sb) sb[o] = make_float2(sr, si);
        if (rb) rb[o] = sr;
        __nv_bfloat16 hr_ = __float2bfloat16_rn(sr);
        __nv_bfloat16 hi_ = __float2bfloat16_rn(si);
        __nv_bfloat16 lr_ = __float2bfloat16_rn(sr - __bfloat162float(hr_));
        __nv_bfloat16 li_ = __float2bfloat16_rn(si - __bfloat162float(hi_));
        sh[o] = __halves2bfloat162(hr_, hi_);
        sl[o] = __halves2bfloat162(lr_, li_);
    }
}

// ---------------------------------------------------------------- LN epi
__global__ __launch_bounds__(256)
void ln_epilogue(float* __restrict__ out)
{
    __shared__ float red[256];
    const int row = blockIdx.x;
    const int tid = threadIdx.x;
    const float* zr = g_z + (size_t)row * OUT_;

    float v[4];
    float s = 0.f;
#pragma unroll
    for (int j = 0; j < 4; ++j) { v[j] = zr[tid + (j << 8)]; s += v[j]; }
    red[tid] = s; __syncthreads();
    for (int off = 128; off > 0; off >>= 1) {
        if (tid < off) red[tid] += red[tid + off];
        __syncthreads();
    }
    float mu = red[0] * (1.f / OUT_);
    __syncthreads();
    float ss = 0.f;
#pragma unroll
    for (int j = 0; j < 4; ++j) { float d = v[j] - mu; ss += d * d; }
    red[tid] = ss; __syncthreads();
    for (int off = 128; off > 0; off >>= 1) {
        if (tid < off) red[tid] += red[tid + off];
        __syncthreads();
    }
    float inv = rsqrtf(red[0] * (1.f / OUT_) + 1e-5f);

    const float* hr = g_h + (size_t)row * HN_;
#pragma unroll
    for (int j = 0; j < 4; ++j) {
        int o = tid + (j << 8);
        float og   = 1.f / (1.f + expf(-hr[MEM_ + OUT_ + MEM_ + o]));
        float thru = hr[MEM_ + o];
        out[(size_t)row * OUT_ + o] = (v[j] - mu) * inv * og + thru * (1.f - og);
    }
}

// ---------------------------------------------------------------- launch
extern "C" void kernel_launch(void* const* d_in, const int* in_sizes, int n_in,
                              void* d_out, int out_size)
{
    (void)in_sizes; (void)n_in;
    const float* x     = (const float*)d_in[0];
    const float* pre_w = (const float*)d_in[1];
    const float* pre_b = (const float*)d_in[2];
    const float* a     = (const float*)d_in[3];
    const float* bfr   = (const float*)d_in[4];
    const float* mix_w = (const float*)d_in[5];
    const float* mix_b = (const float*)d_in[6];
    float* out = (float*)d_out;

    cudaFuncSetAttribute(gemm_mma, cudaFuncAttributeMaxDynamicSharedMemorySize,
                         SMEM_MMA);

    float *hbuf, *zbuf;
    __nv_bfloat16 *xh, *xl, *w1h, *w1l, *w2h, *w2l, *srh, *srl;
    cudaGetSymbolAddress((void**)&hbuf, g_h);
    cudaGetSymbolAddress((void**)&zbuf, g_z);
    cudaGetSymbolAddress((void**)&xh,  g_xh);  cudaGetSymbolAddress((void**)&xl,  g_xl);
    cudaGetSymbolAddress((void**)&w1h, g_w1h); cudaGetSymbolAddress((void**)&w1l, g_w1l);
    cudaGetSymbolAddress((void**)&w2h, g_w2h); cudaGetSymbolAddress((void**)&w2l, g_w2l);
    cudaGetSymbolAddress((void**)&srh, g_srh); cudaGetSymbolAddress((void**)&srl, g_srl);

    const long long OUT_ELEMS = (long long)NTOK * OUT_;        // 16,777,216
    const long long ST_CPLX_F = 2LL * NTOK * MEM_ * C_;        // 67,108,864
    const long long ST_REAL_F = (long long)NTOK * MEM_ * C_;   // 33,554,432
    const long long avail = (long long)out_size - OUT_ELEMS;

    float2* st_i = 0;
    float*  st_r = 0;
    if (avail >= ST_CPLX_F)       st_i = (float2*)(out + OUT_ELEMS);
    else if (avail >= ST_REAL_F)  st_r = out + OUT_ELEMS;

    // input splits (fp32 -> bf16 hi/lo)
    split_kernel<<<(NTOK*IN_/4 + 255)/256, 256>>>(x, xh, xl, NTOK*IN_/4);
    split_kernel<<<(HN_*IN_/4 + 255)/256, 256>>>(pre_w, w1h, w1l, HN_*IN_/4);
    split_kernel<<<(OUT_*KMIX/4 + 255)/256, 256>>>(mix_w, w2h, w2l, OUT_*KMIX/4);

    // 1) h = x @ pre_w^T + pre_b   (M=16384, N=2176, K=1024)
    gemm_mma<<<dim3(HN_/128, NTOK/128), 256, SMEM_MMA>>>(
        xh, xl, w1h, w1l, pre_b, hbuf, IN_, HN_);
    // 2) gated scan input
    gating_kernel<<<(NTOK * MEM_) / 256, 256>>>();
    // 3) scan -> states output + bf16 hi/lo sr
    scan_kernel<<<(B_ * MEM_ * C_) / 256, 256>>>(a, bfr, st_i, st_r);
    // 4) z = sr @ mix_w^T + mix_b  (M=16384, N=1024, K=4096)
    gemm_mma<<<dim3(OUT_/128, NTOK/128), 256, SMEM_MMA>>>(
        srh, srl, w2h, w2l, mix_b, zbuf, KMIX, OUT_);
    // 5) LN + gated mix
    ln_epilogue<<<NTOK, 256>>>(out);
}